// round 15
// baseline (speedup 1.0000x reference)
#include <cuda_runtime.h>
#include <cuda_bf16.h>
#include <math.h>

#define B_    16
#define L_    128
#define V_    32000
#define G4_   4096
#define K_    1024
#define KP_   512     // u32 bf16-pairs per row
#define T_    127
#define M_    2032
#define MPAD_ 2048
#define PD    20      // gemm smem row stride in u32
#define NSLAB 32      // K_/32
#define RS    516     // recurrence smem row stride in u32 (512 + 4 pad)

__device__ float g_X[MPAD_ * K_];
__device__ float g_xall[(size_t)MPAD_ * G4_];
__device__ unsigned g_bar;
// bf16 hi/lo split matrices (u32 = packed bf16x2 along K)
__device__ unsigned g_AH[MPAD_ * KP_], g_AL[MPAD_ * KP_];           // X, then Hs (written by recurrence)
__device__ unsigned g_WH[G4_ * KP_],  g_WL[G4_ * KP_];              // W_ih
__device__ unsigned g_FH[(size_t)V_ * KP_], g_FL[(size_t)V_ * KP_]; // fc_w

// ---------------------------------------------------------------- prep
__global__ void __launch_bounds__(256) prep_kernel(
    const float* __restrict__ latent, const float* __restrict__ emb,
    const int* __restrict__ target, float* __restrict__ out) {
  long i = (long)blockIdx.x * blockDim.x + threadIdx.x;
  if (i == 0) g_bar = 0u;
  const long Z = (long)B_ * (V_ / 4);               // 128000: out l=0 rows
  const long X = (long)M_ * 256;                    // 520192
  if (i < Z) {
    long b = i / 8000, v4 = i % 8000;
    ((float4*)out)[b * ((long)L_ * V_ / 4) + v4] = make_float4(0.f, 0.f, 0.f, 0.f);
  } else if (i < Z + X) {
    long j = i - Z;
    int m = (int)(j / 256), c4 = (int)(j % 256);
    int s = m >> 4, b = m & 15;
    float4 v;
    if (c4 < 128) {
      int tok = target[b * L_ + s];
      v = ((const float4*)emb)[(size_t)tok * 128 + c4];
    } else {
      v = ((const float4*)latent)[b * 128 + (c4 - 128)];
    }
    ((float4*)g_X)[(size_t)m * 256 + c4] = v;
  } else {
    // zero AH/AL rows 2032..2047 (used as h0 = 0 source and gemm tail pad)
    long k = i - Z - X;             // 0..4095
    uint4 z = make_uint4(0u, 0u, 0u, 0u);
    if (k < 2048)
      ((uint4*)(g_AH + (size_t)2032 * KP_))[k] = z;
    else
      ((uint4*)(g_AL + (size_t)2032 * KP_))[k - 2048] = z;
  }
}

// ---------------------------------------------------------------- bf16 split
__device__ __forceinline__ unsigned pack2(__nv_bfloat16 a, __nv_bfloat16 b) {
  __nv_bfloat162 t; t.x = a; t.y = b;
  return *(unsigned*)&t;
}
__device__ __forceinline__ void bsplit2(float x0, float x1, unsigned& h, unsigned& l) {
  __nv_bfloat16 h0 = __float2bfloat16(x0);
  __nv_bfloat16 h1 = __float2bfloat16(x1);
  float r0 = x0 - __bfloat162float(h0);
  float r1 = x1 - __bfloat162float(h1);
  h = pack2(h0, h1);
  l = pack2(__float2bfloat16(r0), __float2bfloat16(r1));
}

__global__ void __launch_bounds__(256) split_kernel(
    const float* __restrict__ src, unsigned* __restrict__ hi,
    unsigned* __restrict__ lo, long npairs) {
  long i = (long)blockIdx.x * blockDim.x + threadIdx.x;
  if (i < npairs) {
    float2 v = ((const float2*)src)[i];
    unsigned h, l;
    bsplit2(v.x, v.y, h, l);
    hi[i] = h; lo[i] = l;
  }
}

// ---------------------------------------------------------------- MMA helpers
__device__ __forceinline__ void mma16(float* c, const unsigned* a, const unsigned* b) {
  asm volatile(
    "mma.sync.aligned.m16n8k16.row.col.f32.bf16.bf16.f32 "
    "{%0,%1,%2,%3}, {%4,%5,%6,%7}, {%8,%9}, {%0,%1,%2,%3};\n"
    : "+f"(c[0]), "+f"(c[1]), "+f"(c[2]), "+f"(c[3])
    : "r"(a[0]), "r"(a[1]), "r"(a[2]), "r"(a[3]), "r"(b[0]), "r"(b[1]));
}
__device__ __forceinline__ void cpa16(unsigned saddr, const void* gptr) {
  asm volatile("cp.async.cg.shared.global [%0], [%1], 16;\n" :: "r"(saddr), "l"(gptr));
}
__device__ __forceinline__ void ldsm4(unsigned& r0, unsigned& r1, unsigned& r2,
                                      unsigned& r3, unsigned saddr) {
  asm volatile("ldmatrix.sync.aligned.m8n8.x4.shared.b16 {%0,%1,%2,%3}, [%4];\n"
               : "=r"(r0), "=r"(r1), "=r"(r2), "=r"(r3) : "r"(saddr));
}

#define TILE_U32 (128 * PD)

// ---------------------------------------------------------------- GEMM (validated R13 version)
template <int EPI>
__global__ void __launch_bounds__(256, 2) gemm_kernel(
    const unsigned* __restrict__ AH, const unsigned* __restrict__ AL,
    const unsigned* __restrict__ BH, const unsigned* __restrict__ BL,
    const float* __restrict__ bias0, const float* __restrict__ bias1,
    float* __restrict__ Cout) {
  extern __shared__ unsigned smem[];   // [2 stages][4 tiles][128*PD]
  const int tid = threadIdx.x, lane = tid & 31, warp = tid >> 5;
  const int wm = warp >> 1, wn = warp & 1, grp = lane >> 2, tig = lane & 3;
  const int m0 = blockIdx.x * 128, n0 = blockIdx.y * 128;

  const unsigned sbase = (unsigned)__cvta_generic_to_shared(smem);
  const int row = tid >> 2, c4 = (tid & 3) * 4;

  const int g8 = lane & 7, q = lane >> 3;
  int offA[2];
#pragma unroll
  for (int mi = 0; mi < 2; mi++)
    offA[mi] = (wm * 32 + mi * 16 + ((q & 1) << 3) + g8) * PD + ((q >> 1) << 2);
  int offB[4];
#pragma unroll
  for (int j = 0; j < 4; j++)
    offB[j] = (wn * 64 + j * 16 + ((q >> 1) << 3) + g8) * PD + ((q & 1) << 2);

  float acc[2][8][4];
#pragma unroll
  for (int a = 0; a < 2; a++)
#pragma unroll
    for (int b = 0; b < 8; b++)
#pragma unroll
      for (int c = 0; c < 4; c++) acc[a][b][c] = 0.f;

  const unsigned* gsrc[4] = {AH, AL, BH, BL};

  auto issue = [&](int st, int kp0) {
#pragma unroll
    for (int t = 0; t < 4; t++) {
      const unsigned* g = gsrc[t];
      int rbase = (t < 2) ? m0 : n0;
      unsigned sdst = sbase + ((st * 4 + t) * TILE_U32) * 4u;
#pragma unroll
      for (int j = 0; j < 2; j++) {
        int r = row + j * 64;
        cpa16(sdst + (r * PD + c4) * 4u,
              g + (size_t)(rbase + r) * KP_ + kp0 + c4);
      }
    }
    asm volatile("cp.async.commit_group;\n");
  };

  issue(0, 0);

  for (int s = 0; s < NSLAB; s++) {
    const int st = s & 1;
    if (s + 1 < NSLAB) {
      issue(st ^ 1, (s + 1) * 16);
      asm volatile("cp.async.wait_group 1;\n");
    } else {
      asm volatile("cp.async.wait_group 0;\n");
    }
    __syncthreads();

    const unsigned ahB = sbase + ((st * 4 + 0) * TILE_U32) * 4u;
    const unsigned alB = sbase + ((st * 4 + 1) * TILE_U32) * 4u;
    const unsigned bhB = sbase + ((st * 4 + 2) * TILE_U32) * 4u;
    const unsigned blB = sbase + ((st * 4 + 3) * TILE_U32) * 4u;

#pragma unroll
    for (int kk = 0; kk < 2; kk++) {
      const int pb4 = kk * 8 * 4;
      unsigned aH[2][4], aL[2][4];
#pragma unroll
      for (int mi = 0; mi < 2; mi++) {
        ldsm4(aH[mi][0], aH[mi][1], aH[mi][2], aH[mi][3], ahB + offA[mi] * 4u + pb4);
        ldsm4(aL[mi][0], aL[mi][1], aL[mi][2], aL[mi][3], alB + offA[mi] * 4u + pb4);
      }
#pragma unroll
      for (int j = 0; j < 4; j++) {
        unsigned bH[4], bL[4];
        ldsm4(bH[0], bH[1], bH[2], bH[3], bhB + offB[j] * 4u + pb4);
        ldsm4(bL[0], bL[1], bL[2], bL[3], blB + offB[j] * 4u + pb4);
#pragma unroll
        for (int mi = 0; mi < 2; mi++) {
          mma16(acc[mi][2 * j],     aH[mi], bH);
          mma16(acc[mi][2 * j],     aH[mi], bL);
          mma16(acc[mi][2 * j],     aL[mi], bH);
          mma16(acc[mi][2 * j + 1], aH[mi], bH + 2);
          mma16(acc[mi][2 * j + 1], aH[mi], bL + 2);
          mma16(acc[mi][2 * j + 1], aL[mi], bH + 2);
        }
      }
    }
    __syncthreads();
  }

#pragma unroll
  for (int mi = 0; mi < 2; mi++)
#pragma unroll
    for (int ni = 0; ni < 8; ni++) {
      int mr = m0 + wm * 32 + mi * 16 + grp;
      int nc = n0 + wn * 64 + ni * 8 + tig * 2;
      float* cp = acc[mi][ni];
      float b0 = bias0[nc] + ((EPI == 0) ? bias1[nc] : 0.f);
      float b1 = bias0[nc + 1] + ((EPI == 0) ? bias1[nc + 1] : 0.f);
      if (EPI == 0) {
        if (mr < M_) {
          g_xall[(size_t)mr * G4_ + nc] = cp[0] + b0;
          g_xall[(size_t)mr * G4_ + nc + 1] = cp[1] + b1;
        }
        if (mr + 8 < M_) {
          g_xall[(size_t)(mr + 8) * G4_ + nc] = cp[2] + b0;
          g_xall[(size_t)(mr + 8) * G4_ + nc + 1] = cp[3] + b1;
        }
      } else {
        if (mr < M_) {
          size_t o = ((size_t)(mr & 15) * L_ + (mr >> 4) + 1) * V_ + nc;
          Cout[o] = cp[0] + b0; Cout[o + 1] = cp[1] + b1;
        }
        if (mr + 8 < M_) {
          int m2 = mr + 8;
          size_t o = ((size_t)(m2 & 15) * L_ + (m2 >> 4) + 1) * V_ + nc;
          Cout[o] = cp[2] + b0; Cout[o + 1] = cp[3] + b1;
        }
      }
    }
}

// ---------------------------------------------------------------- tensor recurrence
// Block bx owns units u0..u0+7 (u0 = 8*bx) => 32 gate rows {g*1024+u0+j}.
// Warps 0-3: MMA (warp w = gate w). Warps 4-7: xall prefetch + LSTM cell,
// write h split directly into g_AH/g_AL row (s*16+b).
__device__ __forceinline__ float sigf(float x) { return 1.f / (1.f + __expf(-x)); }

#define WH_OFF  0
#define WL_OFF  (32 * RS)
#define HH_OFF  (64 * RS)
#define HL_OFF  (80 * RS)
#define GB_OFF  (96 * RS)
#define SM_REC  ((96 * RS + 512) * 4)

__global__ void __launch_bounds__(256) recur_kernel(const float* __restrict__ Whh) {
  extern __shared__ unsigned sm[];
  float* gatesb = (float*)(sm + GB_OFF);
  const int tid = threadIdx.x, lane = tid & 31, warp = tid >> 5;
  const int u0 = blockIdx.x * 8;
  const unsigned sbase = (unsigned)__cvta_generic_to_shared(sm);

  // ---- preload W_hh slice, split into smem (once) ----
  {
    int r = tid >> 3;              // 0..31 smem row (= g*8+j)
    int seg = tid & 7;             // 128-float segment
    int g = r >> 3, j = r & 7;
    const float* src = Whh + ((size_t)(g * K_ + u0 + j)) * K_ + seg * 128;
    unsigned* dh = sm + WH_OFF + r * RS + seg * 64;
    unsigned* dl = sm + WL_OFF + r * RS + seg * 64;
#pragma unroll 8
    for (int p = 0; p < 64; p++) {
      float2 v = ((const float2*)src)[p];
      unsigned hh, ll; bsplit2(v.x, v.y, hh, ll);
      dh[p] = hh; dl[p] = ll;
    }
  }

  // ldmatrix offsets
  const int g8 = lane & 7, q = lane >> 3;
  const int offA = (((q & 1) << 3) + g8) * RS + ((q >> 1) << 2);        // A: h m16
  const int offB = (warp * 8 + g8) * RS + (q << 2);                     // B: gate rows n8 x k32

  float c = 0.f;
  unsigned tgt = 0;

  for (int s = 0; s < T_; s++) {
    // ---- stage h_prev (split pairs) into smem via cp.async ----
    {
#pragma unroll
      for (int k = 0; k < 8; k++) {
        int chunk = tid + k * 256;          // 0..2047
        int row = chunk >> 7;               // batch b
        int pc = (chunk & 127) << 2;        // pair col
        int rsrc = (s == 0) ? (2032 + row) : ((s - 1) * 16 + row);
        cpa16(sbase + (HH_OFF + row * RS + pc) * 4u, g_AH + (size_t)rsrc * KP_ + pc);
        cpa16(sbase + (HL_OFF + row * RS + pc) * 4u, g_AL + (size_t)rsrc * KP_ + pc);
      }
      asm volatile("cp.async.commit_group;\n");
    }

    // cell warps: prefetch xall for this step
    float x0, x1, x2, x3;
    if (tid >= 128) {
      int t = tid - 128, b = t >> 3, j = t & 7;
      const float* xr = g_xall + ((size_t)s * 16 + b) * G4_ + u0 + j;
      x0 = __ldg(xr);
      x1 = __ldg(xr + 1024);
      x2 = __ldg(xr + 2048);
      x3 = __ldg(xr + 3072);
    }

    asm volatile("cp.async.wait_group 0;\n");
    __syncthreads();

    // ---- MMA warps ----
    if (warp < 4) {
      float acc[4] = {0.f, 0.f, 0.f, 0.f};
#pragma unroll 4
      for (int ktp = 0; ktp < 32; ktp++) {
        unsigned bH[4], bL[4];
        ldsm4(bH[0], bH[1], bH[2], bH[3], sbase + (WH_OFF + offB + ktp * 16) * 4u);
        ldsm4(bL[0], bL[1], bL[2], bL[3], sbase + (WL_OFF + offB + ktp * 16) * 4u);
#pragma unroll
        for (int half = 0; half < 2; half++) {
          int kt = 2 * ktp + half;
          unsigned aH[4], aL[4];
          ldsm4(aH[0], aH[1], aH[2], aH[3], sbase + (HH_OFF + offA + kt * 8) * 4u);
          ldsm4(aL[0], aL[1], aL[2], aL[3], sbase + (HL_OFF + offA + kt * 8) * 4u);
          mma16(acc, aH, bH + 2 * half);
          mma16(acc, aH, bL + 2 * half);
          mma16(acc, aL, bH + 2 * half);
        }
      }
      const int grp = lane >> 2, tig = lane & 3;
      gatesb[grp * 32 + warp * 8 + 2 * tig]       = acc[0];
      gatesb[grp * 32 + warp * 8 + 2 * tig + 1]   = acc[1];
      gatesb[(grp + 8) * 32 + warp * 8 + 2 * tig]     = acc[2];
      gatesb[(grp + 8) * 32 + warp * 8 + 2 * tig + 1] = acc[3];
    }
    __syncthreads();

    // ---- cell warps: LSTM update, write split h to g_AH/g_AL ----
    if (tid >= 128) {
      int t = tid - 128, b = t >> 3, j = t & 7;
      float gi = gatesb[b * 32 + j]        + x0;
      float gf = gatesb[b * 32 + 8 + j]    + x1;
      float gg = gatesb[b * 32 + 16 + j]   + x2;
      float go = gatesb[b * 32 + 24 + j]   + x3;
      c = sigf(gf) * c + sigf(gi) * tanhf(gg);
      float h = sigf(go) * tanhf(c);
      float hn = __shfl_down_sync(0xffffffffu, h, 1);
      if ((j & 1) == 0) {
        unsigned ph, pl; bsplit2(h, hn, ph, pl);
        size_t m = (size_t)s * 16 + b;
        g_AH[m * KP_ + (u0 >> 1) + (j >> 1)] = ph;
        g_AL[m * KP_ + (u0 >> 1) + (j >> 1)] = pl;
      }
    }

    __threadfence();
    __syncthreads();
    tgt += gridDim.x;
    if (tid == 0) {
      atomicAdd(&g_bar, 1u);
      while (*(volatile unsigned*)&g_bar < tgt) { __nanosleep(32); }
    }
    __syncthreads();
  }
}

// ---------------------------------------------------------------- launch
extern "C" void kernel_launch(void* const* d_in, const int* in_sizes, int n_in,
                              void* d_out, int out_size) {
  const float* latent = (const float*)d_in[0];
  const float* emb    = (const float*)d_in[1];
  const float* W_ih   = (const float*)d_in[2];
  const float* W_hh   = (const float*)d_in[3];
  const float* b_ih   = (const float*)d_in[4];
  const float* b_hh   = (const float*)d_in[5];
  const float* fc_w   = (const float*)d_in[6];
  const float* fc_b   = (const float*)d_in[7];
  const int*   target = (const int*)d_in[8];
  float* out = (float*)d_out;

  unsigned *AH, *AL, *WH, *WL, *FH, *FL;
  float *Xp;
  cudaGetSymbolAddress((void**)&AH, g_AH);
  cudaGetSymbolAddress((void**)&AL, g_AL);
  cudaGetSymbolAddress((void**)&WH, g_WH);
  cudaGetSymbolAddress((void**)&WL, g_WL);
  cudaGetSymbolAddress((void**)&FH, g_FH);
  cudaGetSymbolAddress((void**)&FL, g_FL);
  cudaGetSymbolAddress((void**)&Xp, g_X);

  const int SM_GEMM = 2 * 4 * TILE_U32 * 4;   // 81920 B
  cudaFuncSetAttribute(gemm_kernel<0>, cudaFuncAttributeMaxDynamicSharedMemorySize, SM_GEMM);
  cudaFuncSetAttribute(gemm_kernel<1>, cudaFuncAttributeMaxDynamicSharedMemorySize, SM_GEMM);
  cudaFuncSetAttribute(recur_kernel, cudaFuncAttributeMaxDynamicSharedMemorySize, SM_REC);

  prep_kernel<<<2548, 256>>>(latent, emb, target, out);

  long npX = (long)MPAD_ * KP_;        // 1,048,576
  long npW = (long)G4_ * KP_;          // 2,097,152
  long npF = (long)V_ * KP_;           // 16,384,000
  split_kernel<<<(unsigned)((npX + 255) / 256), 256>>>(Xp, AH, AL, npX);
  split_kernel<<<(unsigned)((npW + 255) / 256), 256>>>(W_ih, WH, WL, npW);
  split_kernel<<<(unsigned)((npF + 255) / 256), 256>>>(fc_w, FH, FL, npF);

  gemm_kernel<0><<<dim3(16, 32), 256, SM_GEMM>>>(AH, AL, WH, WL, b_ih, b_hh, nullptr);
  recur_kernel<<<128, 256, SM_REC>>>(W_hh);
  gemm_kernel<1><<<dim3(16, 250), 256, SM_GEMM>>>(AH, AL, FH, FL, fc_b, nullptr, out);
}

// round 16
// speedup vs baseline: 1.0474x; 1.0474x over previous
#include <cuda_runtime.h>
#include <cuda_bf16.h>
#include <math.h>

#define B_    16
#define L_    128
#define V_    32000
#define G4_   4096
#define K_    1024
#define KP_   512     // u32 bf16-pairs per row
#define T_    127
#define M_    2032
#define MPAD_ 2048
#define PD    20      // gemm smem row stride in u32
#define NSLAB 32      // K_/32
#define RS    516     // recurrence smem row stride in u32 (512 + 4 pad)

__device__ float g_X[MPAD_ * K_];
__device__ float g_xall[(size_t)MPAD_ * G4_];
__device__ unsigned g_bar;
// bf16 hi/lo split matrices (u32 = packed bf16x2 along K)
__device__ unsigned g_AH[MPAD_ * KP_], g_AL[MPAD_ * KP_];           // X, then Hs (written by recurrence)
__device__ unsigned g_WH[G4_ * KP_],  g_WL[G4_ * KP_];              // W_ih
__device__ unsigned g_FH[(size_t)V_ * KP_], g_FL[(size_t)V_ * KP_]; // fc_w

// ---------------------------------------------------------------- prep
__global__ void __launch_bounds__(256) prep_kernel(
    const float* __restrict__ latent, const float* __restrict__ emb,
    const int* __restrict__ target, float* __restrict__ out) {
  long i = (long)blockIdx.x * blockDim.x + threadIdx.x;
  if (i == 0) g_bar = 0u;
  const long Z = (long)B_ * (V_ / 4);               // 128000: out l=0 rows
  const long X = (long)M_ * 256;                    // 520192
  if (i < Z) {
    long b = i / 8000, v4 = i % 8000;
    ((float4*)out)[b * ((long)L_ * V_ / 4) + v4] = make_float4(0.f, 0.f, 0.f, 0.f);
  } else if (i < Z + X) {
    long j = i - Z;
    int m = (int)(j / 256), c4 = (int)(j % 256);
    int s = m >> 4, b = m & 15;
    float4 v;
    if (c4 < 128) {
      int tok = target[b * L_ + s];
      v = ((const float4*)emb)[(size_t)tok * 128 + c4];
    } else {
      v = ((const float4*)latent)[b * 128 + (c4 - 128)];
    }
    ((float4*)g_X)[(size_t)m * 256 + c4] = v;
  } else {
    // zero AH/AL rows 2032..2047 (used as h0 = 0 source and gemm tail pad)
    long k = i - Z - X;             // 0..4095
    uint4 z = make_uint4(0u, 0u, 0u, 0u);
    if (k < 2048)
      ((uint4*)(g_AH + (size_t)2032 * KP_))[k] = z;
    else
      ((uint4*)(g_AL + (size_t)2032 * KP_))[k - 2048] = z;
  }
}

// ---------------------------------------------------------------- bf16 split
__device__ __forceinline__ unsigned pack2(__nv_bfloat16 a, __nv_bfloat16 b) {
  __nv_bfloat162 t; t.x = a; t.y = b;
  return *(unsigned*)&t;
}
__device__ __forceinline__ void bsplit2(float x0, float x1, unsigned& h, unsigned& l) {
  __nv_bfloat16 h0 = __float2bfloat16(x0);
  __nv_bfloat16 h1 = __float2bfloat16(x1);
  float r0 = x0 - __bfloat162float(h0);
  float r1 = x1 - __bfloat162float(h1);
  h = pack2(h0, h1);
  l = pack2(__float2bfloat16(r0), __float2bfloat16(r1));
}

__global__ void __launch_bounds__(256) split_kernel(
    const float* __restrict__ src, unsigned* __restrict__ hi,
    unsigned* __restrict__ lo, long npairs) {
  long i = (long)blockIdx.x * blockDim.x + threadIdx.x;
  if (i < npairs) {
    float2 v = ((const float2*)src)[i];
    unsigned h, l;
    bsplit2(v.x, v.y, h, l);
    hi[i] = h; lo[i] = l;
  }
}

// ---------------------------------------------------------------- MMA helpers
__device__ __forceinline__ void mma16(float* c, const unsigned* a, const unsigned* b) {
  asm volatile(
    "mma.sync.aligned.m16n8k16.row.col.f32.bf16.bf16.f32 "
    "{%0,%1,%2,%3}, {%4,%5,%6,%7}, {%8,%9}, {%0,%1,%2,%3};\n"
    : "+f"(c[0]), "+f"(c[1]), "+f"(c[2]), "+f"(c[3])
    : "r"(a[0]), "r"(a[1]), "r"(a[2]), "r"(a[3]), "r"(b[0]), "r"(b[1]));
}
__device__ __forceinline__ void cpa16(unsigned saddr, const void* gptr) {
  asm volatile("cp.async.cg.shared.global [%0], [%1], 16;\n" :: "r"(saddr), "l"(gptr));
}
__device__ __forceinline__ void ldsm4(unsigned& r0, unsigned& r1, unsigned& r2,
                                      unsigned& r3, unsigned saddr) {
  asm volatile("ldmatrix.sync.aligned.m8n8.x4.shared.b16 {%0,%1,%2,%3}, [%4];\n"
               : "=r"(r0), "=r"(r1), "=r"(r2), "=r"(r3) : "r"(saddr));
}

#define TILE_U32 (128 * PD)

// ---------------------------------------------------------------- GEMM (validated R13 version)
template <int EPI>
__global__ void __launch_bounds__(256, 2) gemm_kernel(
    const unsigned* __restrict__ AH, const unsigned* __restrict__ AL,
    const unsigned* __restrict__ BH, const unsigned* __restrict__ BL,
    const float* __restrict__ bias0, const float* __restrict__ bias1,
    float* __restrict__ Cout) {
  extern __shared__ unsigned smem[];   // [2 stages][4 tiles][128*PD]
  const int tid = threadIdx.x, lane = tid & 31, warp = tid >> 5;
  const int wm = warp >> 1, wn = warp & 1, grp = lane >> 2, tig = lane & 3;
  const int m0 = blockIdx.x * 128, n0 = blockIdx.y * 128;

  const unsigned sbase = (unsigned)__cvta_generic_to_shared(smem);
  const int row = tid >> 2, c4 = (tid & 3) * 4;

  const int g8 = lane & 7, q = lane >> 3;
  int offA[2];
#pragma unroll
  for (int mi = 0; mi < 2; mi++)
    offA[mi] = (wm * 32 + mi * 16 + ((q & 1) << 3) + g8) * PD + ((q >> 1) << 2);
  int offB[4];
#pragma unroll
  for (int j = 0; j < 4; j++)
    offB[j] = (wn * 64 + j * 16 + ((q >> 1) << 3) + g8) * PD + ((q & 1) << 2);

  float acc[2][8][4];
#pragma unroll
  for (int a = 0; a < 2; a++)
#pragma unroll
    for (int b = 0; b < 8; b++)
#pragma unroll
      for (int c = 0; c < 4; c++) acc[a][b][c] = 0.f;

  const unsigned* gsrc[4] = {AH, AL, BH, BL};

  auto issue = [&](int st, int kp0) {
#pragma unroll
    for (int t = 0; t < 4; t++) {
      const unsigned* g = gsrc[t];
      int rbase = (t < 2) ? m0 : n0;
      unsigned sdst = sbase + ((st * 4 + t) * TILE_U32) * 4u;
#pragma unroll
      for (int j = 0; j < 2; j++) {
        int r = row + j * 64;
        cpa16(sdst + (r * PD + c4) * 4u,
              g + (size_t)(rbase + r) * KP_ + kp0 + c4);
      }
    }
    asm volatile("cp.async.commit_group;\n");
  };

  issue(0, 0);

  for (int s = 0; s < NSLAB; s++) {
    const int st = s & 1;
    if (s + 1 < NSLAB) {
      issue(st ^ 1, (s + 1) * 16);
      asm volatile("cp.async.wait_group 1;\n");
    } else {
      asm volatile("cp.async.wait_group 0;\n");
    }
    __syncthreads();

    const unsigned ahB = sbase + ((st * 4 + 0) * TILE_U32) * 4u;
    const unsigned alB = sbase + ((st * 4 + 1) * TILE_U32) * 4u;
    const unsigned bhB = sbase + ((st * 4 + 2) * TILE_U32) * 4u;
    const unsigned blB = sbase + ((st * 4 + 3) * TILE_U32) * 4u;

#pragma unroll
    for (int kk = 0; kk < 2; kk++) {
      const int pb4 = kk * 8 * 4;
      unsigned aH[2][4], aL[2][4];
#pragma unroll
      for (int mi = 0; mi < 2; mi++) {
        ldsm4(aH[mi][0], aH[mi][1], aH[mi][2], aH[mi][3], ahB + offA[mi] * 4u + pb4);
        ldsm4(aL[mi][0], aL[mi][1], aL[mi][2], aL[mi][3], alB + offA[mi] * 4u + pb4);
      }
#pragma unroll
      for (int j = 0; j < 4; j++) {
        unsigned bH[4], bL[4];
        ldsm4(bH[0], bH[1], bH[2], bH[3], bhB + offB[j] * 4u + pb4);
        ldsm4(bL[0], bL[1], bL[2], bL[3], blB + offB[j] * 4u + pb4);
#pragma unroll
        for (int mi = 0; mi < 2; mi++) {
          mma16(acc[mi][2 * j],     aH[mi], bH);
          mma16(acc[mi][2 * j],     aH[mi], bL);
          mma16(acc[mi][2 * j],     aL[mi], bH);
          mma16(acc[mi][2 * j + 1], aH[mi], bH + 2);
          mma16(acc[mi][2 * j + 1], aH[mi], bL + 2);
          mma16(acc[mi][2 * j + 1], aL[mi], bH + 2);
        }
      }
    }
    __syncthreads();
  }

#pragma unroll
  for (int mi = 0; mi < 2; mi++)
#pragma unroll
    for (int ni = 0; ni < 8; ni++) {
      int mr = m0 + wm * 32 + mi * 16 + grp;
      int nc = n0 + wn * 64 + ni * 8 + tig * 2;
      float* cp = acc[mi][ni];
      float b0 = bias0[nc] + ((EPI == 0) ? bias1[nc] : 0.f);
      float b1 = bias0[nc + 1] + ((EPI == 0) ? bias1[nc + 1] : 0.f);
      if (EPI == 0) {
        if (mr < M_) {
          g_xall[(size_t)mr * G4_ + nc] = cp[0] + b0;
          g_xall[(size_t)mr * G4_ + nc + 1] = cp[1] + b1;
        }
        if (mr + 8 < M_) {
          g_xall[(size_t)(mr + 8) * G4_ + nc] = cp[2] + b0;
          g_xall[(size_t)(mr + 8) * G4_ + nc + 1] = cp[3] + b1;
        }
      } else {
        if (mr < M_) {
          size_t o = ((size_t)(mr & 15) * L_ + (mr >> 4) + 1) * V_ + nc;
          Cout[o] = cp[0] + b0; Cout[o + 1] = cp[1] + b1;
        }
        if (mr + 8 < M_) {
          int m2 = mr + 8;
          size_t o = ((size_t)(m2 & 15) * L_ + (m2 >> 4) + 1) * V_ + nc;
          Cout[o] = cp[2] + b0; Cout[o + 1] = cp[3] + b1;
        }
      }
    }
}

// ---------------------------------------------------------------- tensor recurrence
// Block bx owns units u0..u0+7 => 32 gate rows. ALL 8 warps do MMA:
// warp w: gate (w&3), K-half (w>>2) -> 96 MMAs in 3 independent chains.
// Partial gates reduced via smem; cell on tid>=128 adds K-halves + xall.
__device__ __forceinline__ float sigf(float x) { return 1.f / (1.f + __expf(-x)); }

#define WH_OFF  0
#define WL_OFF  (32 * RS)
#define HH_OFF  (64 * RS)
#define HL_OFF  (80 * RS)
#define GB_OFF  (96 * RS)
#define SM_REC  ((96 * RS + 1024) * 4)

__global__ void __launch_bounds__(256) recur_kernel(const float* __restrict__ Whh) {
  extern __shared__ unsigned sm[];
  float* gatesb = (float*)(sm + GB_OFF);   // [2][16][32]
  const int tid = threadIdx.x, lane = tid & 31, warp = tid >> 5;
  const int u0 = blockIdx.x * 8;
  const unsigned sbase = (unsigned)__cvta_generic_to_shared(sm);

  // ---- preload W_hh slice, split into smem (once) ----
  {
    int r = tid >> 3;              // 0..31 smem row (= g*8+j)
    int seg = tid & 7;             // 128-float segment
    int g = r >> 3, j = r & 7;
    const float* src = Whh + ((size_t)(g * K_ + u0 + j)) * K_ + seg * 128;
    unsigned* dh = sm + WH_OFF + r * RS + seg * 64;
    unsigned* dl = sm + WL_OFF + r * RS + seg * 64;
#pragma unroll 8
    for (int p = 0; p < 64; p++) {
      float2 v = ((const float2*)src)[p];
      unsigned hh, ll; bsplit2(v.x, v.y, hh, ll);
      dh[p] = hh; dl[p] = ll;
    }
  }

  // ldmatrix offsets
  const int g8 = lane & 7, q = lane >> 3;
  const int gate = warp & 3, kh = warp >> 2;
  const int kbase = kh * 256;                                         // K-half offset (u32)
  const int offA = (((q & 1) << 3) + g8) * RS + ((q >> 1) << 2) + kbase;
  const int offB = (gate * 8 + g8) * RS + (q << 2) + kbase;

  float c = 0.f;
  unsigned tgt = 0;

  for (int s = 0; s < T_; s++) {
    // ---- stage h_prev (split pairs) into smem via cp.async ----
    {
#pragma unroll
      for (int k = 0; k < 8; k++) {
        int chunk = tid + k * 256;          // 0..2047
        int row = chunk >> 7;               // batch b
        int pc = (chunk & 127) << 2;        // pair col
        int rsrc = (s == 0) ? (2032 + row) : ((s - 1) * 16 + row);
        cpa16(sbase + (HH_OFF + row * RS + pc) * 4u, g_AH + (size_t)rsrc * KP_ + pc);
        cpa16(sbase + (HL_OFF + row * RS + pc) * 4u, g_AL + (size_t)rsrc * KP_ + pc);
      }
      asm volatile("cp.async.commit_group;\n");
    }

    // cell threads: prefetch xall for this step (overlaps cp.async)
    float x0, x1, x2, x3;
    if (tid >= 128) {
      int t = tid - 128, b = t >> 3, j = t & 7;
      const float* xr = g_xall + ((size_t)s * 16 + b) * G4_ + u0 + j;
      x0 = __ldg(xr);
      x1 = __ldg(xr + 1024);
      x2 = __ldg(xr + 2048);
      x3 = __ldg(xr + 3072);
    }

    asm volatile("cp.async.wait_group 0;\n");
    __syncthreads();

    // ---- MMA: all 8 warps, 3 independent accumulator chains ----
    {
      float aA[4] = {0.f, 0.f, 0.f, 0.f};
      float aB[4] = {0.f, 0.f, 0.f, 0.f};
      float aC[4] = {0.f, 0.f, 0.f, 0.f};
#pragma unroll 4
      for (int ktp = 0; ktp < 16; ktp++) {
        unsigned bH[4], bL[4];
        ldsm4(bH[0], bH[1], bH[2], bH[3], sbase + (WH_OFF + offB + ktp * 16) * 4u);
        ldsm4(bL[0], bL[1], bL[2], bL[3], sbase + (WL_OFF + offB + ktp * 16) * 4u);
#pragma unroll
        for (int half = 0; half < 2; half++) {
          int kt = 2 * ktp + half;
          unsigned aH[4], aL[4];
          ldsm4(aH[0], aH[1], aH[2], aH[3], sbase + (HH_OFF + offA + kt * 8) * 4u);
          ldsm4(aL[0], aL[1], aL[2], aL[3], sbase + (HL_OFF + offA + kt * 8) * 4u);
          mma16(aA, aH, bH + 2 * half);
          mma16(aB, aH, bL + 2 * half);
          mma16(aC, aL, bH + 2 * half);
        }
      }
      const int grp = lane >> 2, tig = lane & 3;
      float* gb = gatesb + kh * 512;
      gb[grp * 32 + gate * 8 + 2 * tig]           = aA[0] + aB[0] + aC[0];
      gb[grp * 32 + gate * 8 + 2 * tig + 1]       = aA[1] + aB[1] + aC[1];
      gb[(grp + 8) * 32 + gate * 8 + 2 * tig]     = aA[2] + aB[2] + aC[2];
      gb[(grp + 8) * 32 + gate * 8 + 2 * tig + 1] = aA[3] + aB[3] + aC[3];
    }
    __syncthreads();

    // ---- cell: LSTM update, write split h to g_AH/g_AL ----
    if (tid >= 128) {
      int t = tid - 128, b = t >> 3, j = t & 7;
      float gi = gatesb[b * 32 + j]      + gatesb[512 + b * 32 + j]      + x0;
      float gf = gatesb[b * 32 + 8 + j]  + gatesb[512 + b * 32 + 8 + j]  + x1;
      float gg = gatesb[b * 32 + 16 + j] + gatesb[512 + b * 32 + 16 + j] + x2;
      float go = gatesb[b * 32 + 24 + j] + gatesb[512 + b * 32 + 24 + j] + x3;
      c = sigf(gf) * c + sigf(gi) * tanhf(gg);
      float h = sigf(go) * tanhf(c);
      float hn = __shfl_down_sync(0xffffffffu, h, 1);
      if ((j & 1) == 0) {
        unsigned ph, pl; bsplit2(h, hn, ph, pl);
        size_t m = (size_t)s * 16 + b;
        g_AH[m * KP_ + (u0 >> 1) + (j >> 1)] = ph;
        g_AL[m * KP_ + (u0 >> 1) + (j >> 1)] = pl;
      }
    }

    __threadfence();
    __syncthreads();
    tgt += gridDim.x;
    if (tid == 0) {
      atomicAdd(&g_bar, 1u);
      while (*(volatile unsigned*)&g_bar < tgt) {}
    }
    __syncthreads();
  }
}

// ---------------------------------------------------------------- launch
extern "C" void kernel_launch(void* const* d_in, const int* in_sizes, int n_in,
                              void* d_out, int out_size) {
  const float* latent = (const float*)d_in[0];
  const float* emb    = (const float*)d_in[1];
  const float* W_ih   = (const float*)d_in[2];
  const float* W_hh   = (const float*)d_in[3];
  const float* b_ih   = (const float*)d_in[4];
  const float* b_hh   = (const float*)d_in[5];
  const float* fc_w   = (const float*)d_in[6];
  const float* fc_b   = (const float*)d_in[7];
  const int*   target = (const int*)d_in[8];
  float* out = (float*)d_out;

  unsigned *AH, *AL, *WH, *WL, *FH, *FL;
  float *Xp;
  cudaGetSymbolAddress((void**)&AH, g_AH);
  cudaGetSymbolAddress((void**)&AL, g_AL);
  cudaGetSymbolAddress((void**)&WH, g_WH);
  cudaGetSymbolAddress((void**)&WL, g_WL);
  cudaGetSymbolAddress((void**)&FH, g_FH);
  cudaGetSymbolAddress((void**)&FL, g_FL);
  cudaGetSymbolAddress((void**)&Xp, g_X);

  const int SM_GEMM = 2 * 4 * TILE_U32 * 4;   // 81920 B
  cudaFuncSetAttribute(gemm_kernel<0>, cudaFuncAttributeMaxDynamicSharedMemorySize, SM_GEMM);
  cudaFuncSetAttribute(gemm_kernel<1>, cudaFuncAttributeMaxDynamicSharedMemorySize, SM_GEMM);
  cudaFuncSetAttribute(recur_kernel, cudaFuncAttributeMaxDynamicSharedMemorySize, SM_REC);

  prep_kernel<<<2548, 256>>>(latent, emb, target, out);

  long npX = (long)MPAD_ * KP_;        // 1,048,576
  long npW = (long)G4_ * KP_;          // 2,097,152
  long npF = (long)V_ * KP_;           // 16,384,000
  split_kernel<<<(unsigned)((npX + 255) / 256), 256>>>(Xp, AH, AL, npX);
  split_kernel<<<(unsigned)((npW + 255) / 256), 256>>>(W_ih, WH, WL, npW);
  split_kernel<<<(unsigned)((npF + 255) / 256), 256>>>(fc_w, FH, FL, npF);

  gemm_kernel<0><<<dim3(16, 32), 256, SM_GEMM>>>(AH, AL, WH, WL, b_ih, b_hh, nullptr);
  recur_kernel<<<128, 256, SM_REC>>>(W_hh);
  gemm_kernel<1><<<dim3(16, 250), 256, SM_GEMM>>>(AH, AL, FH, FL, fc_b, nullptr, out);
}